// round 15
// baseline (speedup 1.0000x reference)
#include <cuda_runtime.h>
#include <cuda_bf16.h>
#include <cstdint>

// Problem constants
#define BB 2
#define NN 64
#define DD 256
#define HH 8
#define DK 32
#define MTOT (BB*NN*NN)   // 8192 rows

typedef unsigned long long u64;

// ---------------- scratch (no allocations allowed) ----------------
__device__ float g_lv[MTOT * DD];
__device__ float g_rv[MTOT * DD];
__device__ __nv_bfloat16 g_shi[MTOT * DD];
__device__ __nv_bfloat16 g_slo[MTOT * DD];
__device__ __nv_bfloat16 g_xhi[MTOT * DD];
__device__ __nv_bfloat16 g_xlo[MTOT * DD];
__device__ __nv_bfloat16 g_whi[5 * DD * DD];
__device__ __nv_bfloat16 g_wlo[5 * DD * DD];
__device__ __nv_bfloat16 g_lkhi[MTOT * DD];
__device__ __nv_bfloat16 g_lklo[MTOT * DD];
__device__ __nv_bfloat16 g_rkhi[MTOT * DD];
__device__ __nv_bfloat16 g_rklo[MTOT * DD];
__device__ float g_E[16 * NN * NN * NN];     // [bh][a][x][y]

// ---------------- f32x2 helpers ----------------
__device__ __forceinline__ u64 pack2(float lo, float hi) {
    u64 r; asm("mov.b64 %0, {%1,%2};" : "=l"(r) : "f"(lo), "f"(hi)); return r;
}
__device__ __forceinline__ void unpack2(u64 v, float& lo, float& hi) {
    asm("mov.b64 {%0,%1}, %2;" : "=f"(lo), "=f"(hi) : "l"(v));
}
__device__ __forceinline__ void ffma2(u64& d, u64 a, u64 b) {
    asm("fma.rn.f32x2 %0, %1, %2, %0;" : "+l"(d) : "l"(a), "l"(b));
}
__device__ __forceinline__ void mul2(u64& d, u64 a, u64 b) {
    asm("mul.rn.f32x2 %0, %1, %2;" : "=l"(d) : "l"(a), "l"(b));
}

__device__ __forceinline__ uint32_t smem_u32(const void* p) {
    uint32_t a;
    asm("{ .reg .u64 t; cvta.to.shared.u64 t, %1; cvt.u32.u64 %0, t; }"
        : "=r"(a) : "l"(p));
    return a;
}

// ---------------- HMMA / cp.async helpers -----------------
__device__ __forceinline__ void ldsm_x4(uint32_t& r0, uint32_t& r1,
                                        uint32_t& r2, uint32_t& r3, uint32_t addr) {
    asm volatile("ldmatrix.sync.aligned.m8n8.x4.shared.b16 {%0,%1,%2,%3}, [%4];"
                 : "=r"(r0), "=r"(r1), "=r"(r2), "=r"(r3) : "r"(addr));
}
__device__ __forceinline__ void ldsm_x2(uint32_t& r0, uint32_t& r1, uint32_t addr) {
    asm volatile("ldmatrix.sync.aligned.m8n8.x2.shared.b16 {%0,%1}, [%2];"
                 : "=r"(r0), "=r"(r1) : "r"(addr));
}
__device__ __forceinline__ void mma_bf16(float* c, const uint32_t* a, const uint32_t* b) {
    asm volatile("mma.sync.aligned.m16n8k16.row.col.f32.bf16.bf16.f32 "
                 "{%0,%1,%2,%3}, {%4,%5,%6,%7}, {%8,%9}, {%0,%1,%2,%3};"
                 : "+f"(c[0]), "+f"(c[1]), "+f"(c[2]), "+f"(c[3])
                 : "r"(a[0]), "r"(a[1]), "r"(a[2]), "r"(a[3]), "r"(b[0]), "r"(b[1]));
}
__device__ __forceinline__ void cp_async16(uint32_t dst, const void* src) {
    asm volatile("cp.async.ca.shared.global [%0], [%1], 16;" :: "r"(dst), "l"(src));
}
#define CP_COMMIT() asm volatile("cp.async.commit_group;" ::: "memory")
#define CP_WAIT(N)  asm volatile("cp.async.wait_group %0;" :: "n"(N) : "memory")

// split fp32 -> (hi, lo) bf16 pairs
__device__ __forceinline__ void split4(float4 v, uint2& hi, uint2& lo) {
    __nv_bfloat16 h0 = __float2bfloat16(v.x), h1 = __float2bfloat16(v.y);
    __nv_bfloat16 h2 = __float2bfloat16(v.z), h3 = __float2bfloat16(v.w);
    __nv_bfloat16 l0 = __float2bfloat16(v.x - __bfloat162float(h0));
    __nv_bfloat16 l1 = __float2bfloat16(v.y - __bfloat162float(h1));
    __nv_bfloat16 l2 = __float2bfloat16(v.z - __bfloat162float(h2));
    __nv_bfloat16 l3 = __float2bfloat16(v.w - __bfloat162float(h3));
    __nv_bfloat162 hp0 = __halves2bfloat162(h0, h1);
    __nv_bfloat162 hp1 = __halves2bfloat162(h2, h3);
    __nv_bfloat162 lp0 = __halves2bfloat162(l0, l1);
    __nv_bfloat162 lp1 = __halves2bfloat162(l2, l3);
    hi.x = *(uint32_t*)&hp0; hi.y = *(uint32_t*)&hp1;
    lo.x = *(uint32_t*)&lp0; lo.y = *(uint32_t*)&lp1;
}
__device__ __forceinline__ void split2(float x, float y, uint32_t& hi, uint32_t& lo) {
    __nv_bfloat16 h0 = __float2bfloat16(x), h1 = __float2bfloat16(y);
    __nv_bfloat16 l0 = __float2bfloat16(x - __bfloat162float(h0));
    __nv_bfloat16 l1 = __float2bfloat16(y - __bfloat162float(h1));
    __nv_bfloat162 hp = __halves2bfloat162(h0, h1);
    __nv_bfloat162 lp = __halves2bfloat162(l0, l1);
    hi = *(uint32_t*)&hp; lo = *(uint32_t*)&lp;
}

// ---------------- merged convert kernel (state + all 5 weights) --------
#define NS4 (MTOT * DD / 4)        // 524288 state float4s
#define NW4 (5 * DD * DD / 4)      // 81920 weight float4s
struct WSrc { const float* w[5]; };

__global__ void conv_all_kernel(const float* __restrict__ state, WSrc ws,
                                __nv_bfloat16* __restrict__ shi,
                                __nv_bfloat16* __restrict__ slo,
                                __nv_bfloat16* __restrict__ whi,
                                __nv_bfloat16* __restrict__ wlo)
{
    int i = blockIdx.x * 256 + threadIdx.x;
    if (i < NS4) {
        float4 v = ((const float4*)state)[i];
        uint2 h, l;
        split4(v, h, l);
        ((uint2*)shi)[i] = h;
        ((uint2*)slo)[i] = l;
    } else if (i < NS4 + NW4) {
        int j = i - NS4;
        int which = j >> 14;
        int off = j & 16383;
        float4 v = ((const float4*)ws.w[which])[off];
        uint2 h, l;
        split4(v, h, l);
        ((uint2*)whi)[j] = h;
        ((uint2*)wlo)[j] = l;
    }
}

// ================= bf16-split HMMA GEMM =============
struct GemmIO {
    const float* bias[4];
    float* out[4];
    __nv_bfloat16* hi[4];
    __nv_bfloat16* lo[4];
};

#define GROW 80
#define GMAT (128 * GROW)
#define GSTAGE (4 * GMAT)
#define GEMM_SMEM (2 * GSTAGE)  // 81920

__global__ void __launch_bounds__(256) gemm_bf16_kernel(
    const __nv_bfloat16* __restrict__ Ahi, const __nv_bfloat16* __restrict__ Alo,
    const __nv_bfloat16* __restrict__ Whi, const __nv_bfloat16* __restrict__ Wlo,
    int wbase, GemmIO io)
{
    extern __shared__ unsigned char smg[];
    const uint32_t smb = smem_u32(smg);

    const int tid = threadIdx.x;
    const int wid = tid >> 5;
    const int lane = tid & 31;
    const int m0 = blockIdx.x * 128;
    const int by = blockIdx.y;
    const int sel = by >> 1;
    const int n0 = (by & 1) * 128;
    const int woff = (wbase + sel) * DD * DD;
    const float* __restrict__ bias = io.bias[sel];
    float* __restrict__ C = io.out[sel];
    __nv_bfloat16* __restrict__ Chi = io.hi[sel];
    __nv_bfloat16* __restrict__ Clo = io.lo[sel];

    const int wm = wid & 1;
    const int wn = wid >> 1;

    float acc[4][4][4];
    #pragma unroll
    for (int i = 0; i < 4; i++)
        #pragma unroll
        for (int j = 0; j < 4; j++)
            #pragma unroll
            for (int q = 0; q < 4; q++) acc[i][j][q] = 0.f;

    auto issue = [&](int kt, int st) {
        const int kc = kt * 32;
        const uint32_t sb = smb + st * GSTAGE;
        #pragma unroll
        for (int t = 0; t < 8; t++) {
            int i = tid + (t << 8);
            int mat = t >> 1;
            int r = (i >> 2) & 127;
            int c = i & 3;
            uint32_t dst = sb + mat * GMAT + r * GROW + c * 16;
            const __nv_bfloat16* src;
            if (mat == 0)      src = Ahi + (m0 + r) * DD + kc + c * 8;
            else if (mat == 1) src = Alo + (m0 + r) * DD + kc + c * 8;
            else if (mat == 2) src = Whi + woff + (n0 + r) * DD + kc + c * 8;
            else               src = Wlo + woff + (n0 + r) * DD + kc + c * 8;
            cp_async16(dst, src);
        }
        CP_COMMIT();
    };

    auto compute = [&](int st) {
        const uint32_t sAhi = smb + st * GSTAGE;
        const uint32_t sAlo = sAhi + GMAT;
        const uint32_t sWhi = sAhi + 2 * GMAT;
        const uint32_t sWlo = sAhi + 3 * GMAT;
        #pragma unroll
        for (int ks = 0; ks < 2; ks++) {
            const uint32_t kb = ks * 32;
            uint32_t ah[4][4], al[4][4], bh[4][2], bl[4][2];
            const uint32_t aoff = (wm * 64 + (lane & 15)) * GROW + kb + ((lane >> 4) << 4);
            #pragma unroll
            for (int mi = 0; mi < 4; mi++) {
                ldsm_x4(ah[mi][0], ah[mi][1], ah[mi][2], ah[mi][3],
                        sAhi + aoff + mi * 16 * GROW);
                ldsm_x4(al[mi][0], al[mi][1], al[mi][2], al[mi][3],
                        sAlo + aoff + mi * 16 * GROW);
            }
            const uint32_t boff = (wn * 32 + (lane & 7)) * GROW + kb + (((lane >> 3) & 1) << 4);
            #pragma unroll
            for (int ni = 0; ni < 4; ni++) {
                ldsm_x2(bh[ni][0], bh[ni][1], sWhi + boff + ni * 8 * GROW);
                ldsm_x2(bl[ni][0], bl[ni][1], sWlo + boff + ni * 8 * GROW);
            }
            #pragma unroll
            for (int mi = 0; mi < 4; mi++)
                #pragma unroll
                for (int ni = 0; ni < 4; ni++) mma_bf16(acc[mi][ni], ah[mi], bh[ni]);
            #pragma unroll
            for (int mi = 0; mi < 4; mi++)
                #pragma unroll
                for (int ni = 0; ni < 4; ni++) mma_bf16(acc[mi][ni], ah[mi], bl[ni]);
            #pragma unroll
            for (int mi = 0; mi < 4; mi++)
                #pragma unroll
                for (int ni = 0; ni < 4; ni++) mma_bf16(acc[mi][ni], al[mi], bh[ni]);
        }
    };

    issue(0, 0);
    for (int kt = 0; kt < 8; kt++) {
        if (kt < 7) {
            issue(kt + 1, (kt + 1) & 1);
            CP_WAIT(1);
        } else {
            CP_WAIT(0);
        }
        __syncthreads();
        compute(kt & 1);
        __syncthreads();
    }

    // epilogue: fp32 and/or bf16 hi/lo stores (each optional)
    #pragma unroll
    for (int mi = 0; mi < 4; mi++) {
        const int mlo = m0 + wm * 64 + mi * 16 + (lane >> 2);
        #pragma unroll
        for (int ni = 0; ni < 4; ni++) {
            const int nb = n0 + wn * 32 + ni * 8 + ((lane & 3) << 1);
            const float2 bv = *(const float2*)&bias[nb];
            float2 o0, o1;
            o0.x = acc[mi][ni][0] + bv.x; o0.y = acc[mi][ni][1] + bv.y;
            o1.x = acc[mi][ni][2] + bv.x; o1.y = acc[mi][ni][3] + bv.y;
            if (C) {
                *(float2*)&C[mlo * DD + nb] = o0;
                *(float2*)&C[(mlo + 8) * DD + nb] = o1;
            }
            if (Chi) {
                uint32_t h, l;
                split2(o0.x, o0.y, h, l);
                *(uint32_t*)&Chi[mlo * DD + nb] = h;
                *(uint32_t*)&Clo[mlo * DD + nb] = l;
                split2(o1.x, o1.y, h, l);
                *(uint32_t*)&Chi[(mlo + 8) * DD + nb] = h;
                *(uint32_t*)&Clo[(mlo + 8) * DD + nb] = l;
            }
        }
    }
}

// ================= scores kernel v2 (2 a per stage, 4 warps per a) =====
#define SC_ROW 80
#define SC_MAT (64 * SC_ROW)          // 5120 bytes per matrix
#define SC_A   (4 * SC_MAT)           // 20480 per a
#define SC_STG (2 * SC_A)             // 40960 per stage (2 a)
#define SC_SMEM (2 * SC_STG)          // 81920

__global__ void __launch_bounds__(256) scores_kernel(
    const __nv_bfloat16* __restrict__ LKhi, const __nv_bfloat16* __restrict__ LKlo,
    const __nv_bfloat16* __restrict__ RKhi, const __nv_bfloat16* __restrict__ RKlo,
    const unsigned char* __restrict__ mask, float* __restrict__ E)
{
    extern __shared__ unsigned char sms[];
    const uint32_t smb = smem_u32(sms);
    const int tid = threadIdx.x;
    const int wid = tid >> 5, lane = tid & 31;
    const int bh = blockIdx.y;
    const int b = bh >> 3, h = bh & 7;
    const int a0c = blockIdx.x * 8;
    const int ai = wid >> 2;
    const int wm = wid & 3;

    auto issue = [&](int a0, int st) {
        const uint32_t sb = smb + st * SC_STG;
        #pragma unroll
        for (int t = 0; t < 8; t++) {
            int idx = tid + (t << 8);
            int aidx = idx >> 10;
            int mat = (idx >> 8) & 3;
            int r = (idx >> 2) & 63;
            int c = idx & 3;
            uint32_t dst = sb + aidx * SC_A + mat * SC_MAT + r * SC_ROW + c * 16;
            const int a = a0 + aidx;
            const __nv_bfloat16* src;
            if (mat == 0)      src = LKhi + ((b * NN + r) * NN + a) * DD + h * DK + c * 8;
            else if (mat == 1) src = LKlo + ((b * NN + r) * NN + a) * DD + h * DK + c * 8;
            else if (mat == 2) src = RKhi + ((b * NN + a) * NN + r) * DD + h * DK + c * 8;
            else               src = RKlo + ((b * NN + a) * NN + r) * DD + h * DK + c * 8;
            cp_async16(dst, src);
        }
        CP_COMMIT();
    };

    const float scale = 0.17677669529663687f;   // 1/sqrt(32)

    issue(a0c, 0);
    for (int it = 0; it < 4; it++) {
        const int a = a0c + it * 2 + ai;
        if (it < 3) { issue(a0c + (it + 1) * 2, (it + 1) & 1); CP_WAIT(1); }
        else CP_WAIT(0);
        __syncthreads();

        const uint32_t base = smb + (it & 1) * SC_STG + ai * SC_A;
        const uint32_t sLKh = base, sLKl = base + SC_MAT;
        const uint32_t sRKh = base + 2 * SC_MAT, sRKl = base + 3 * SC_MAT;

        float acc[8][4];
        #pragma unroll
        for (int nf = 0; nf < 8; nf++)
            #pragma unroll
            for (int q = 0; q < 4; q++) acc[nf][q] = 0.f;

        #pragma unroll
        for (int ks = 0; ks < 2; ks++) {
            const uint32_t kb = ks * 32;
            uint32_t ah[4], al[4], bhf[8][2], blf[8][2];
            const uint32_t aoff = (wm * 16 + (lane & 15)) * SC_ROW + kb + ((lane >> 4) << 4);
            ldsm_x4(ah[0], ah[1], ah[2], ah[3], sLKh + aoff);
            ldsm_x4(al[0], al[1], al[2], al[3], sLKl + aoff);
            const uint32_t brow = (lane & 7) + ((lane >> 4) << 3);
            const uint32_t bcol = kb + (((lane >> 3) & 1) << 4);
            #pragma unroll
            for (int nb = 0; nb < 4; nb++) {
                const uint32_t boff = (nb * 16 + brow) * SC_ROW + bcol;
                ldsm_x4(bhf[2 * nb][0], bhf[2 * nb][1], bhf[2 * nb + 1][0],
                        bhf[2 * nb + 1][1], sRKh + boff);
                ldsm_x4(blf[2 * nb][0], blf[2 * nb][1], blf[2 * nb + 1][0],
                        blf[2 * nb + 1][1], sRKl + boff);
            }
            #pragma unroll
            for (int nf = 0; nf < 8; nf++) mma_bf16(acc[nf], ah, bhf[nf]);
            #pragma unroll
            for (int nf = 0; nf < 8; nf++) mma_bf16(acc[nf], ah, blf[nf]);
            #pragma unroll
            for (int nf = 0; nf < 8; nf++) mma_bf16(acc[nf], al, bhf[nf]);
        }

        // exp + mask + store E[bh][a][x][y]
        const int r0 = wm * 16 + (lane >> 2);
        #pragma unroll
        for (int nf = 0; nf < 8; nf++) {
            const int col = nf * 8 + ((lane & 3) << 1);
            const unsigned char* mp0 = mask + ((b * NN + r0) * NN + a) * NN + col;
            const unsigned char* mp1 = mask + ((b * NN + r0 + 8) * NN + a) * NN + col;
            float2 e0, e1;
            e0.x = mp0[0] ? 0.f : __expf(acc[nf][0] * scale);
            e0.y = mp0[1] ? 0.f : __expf(acc[nf][1] * scale);
            e1.x = mp1[0] ? 0.f : __expf(acc[nf][2] * scale);
            e1.y = mp1[1] ? 0.f : __expf(acc[nf][3] * scale);
            float* ep = E + ((bh * NN + a) * NN + r0) * NN + col;
            *(float2*)ep = e0;
            *(float2*)(ep + 8 * NN) = e1;
        }
        __syncthreads();
    }
}

// ================= combine kernel v5 (512 thr, depth-2 prefetch) =======
// out[x,y,d] = (sum_a E[a,x,y]*LV[x,a,d]*RV[a,y,d]) / (sum_a E[a,x,y])
// Thread = (y, d-eighth). All loads are L2 hits (~250cyc): double-buffered
// register prefetch 2 a ahead covers the latency without barriers.
#define CXT 8
#define CMB_SMEM (CXT * NN * DK * 4)    // 65536 bytes (LVs)

__global__ void __launch_bounds__(512) combine_kernel(
    const float* __restrict__ LV, const float* __restrict__ RV,
    const float* __restrict__ E,
    __nv_bfloat16* __restrict__ Ohi, __nv_bfloat16* __restrict__ Olo)
{
    extern __shared__ float LVs[];     // [8x][64a][32d]

    const int tid = threadIdx.x;
    const int blk = blockIdx.x;        // 128 = bh(16)*xt(8)
    const int xt = blk & 7;
    const int bh = blk >> 3;
    const int b = bh >> 3, h = bh & 7;
    const int x0 = xt << 3;

    const int y  = tid >> 3;           // 0..63
    const int q  = tid & 7;            // d-eighth
    const int qd = q << 2;             // 0,4,...,28

    for (int i = tid; i < CXT * NN * DK / 4; i += 512) {
        int xv = i >> 9;
        int a  = (i >> 3) & 63;
        int d4 = (i & 7) << 2;
        *(float4*)&LVs[((xv << 6) + a) * DK + d4] =
            *(const float4*)&LV[((b * NN + x0 + xv) * NN + a) * DD + h * DK + d4];
    }
    __syncthreads();

    const float* rvb = RV + (b * NN * NN + y) * DD + h * DK + qd;
    const float* eb  = E + (bh * NN * NN + x0) * NN + y;

    // depth-2 double-buffered register prefetch
    float4 rn[2];
    float en[2][CXT];
    auto ldg_a = [&](int a, int buf) {
        rn[buf] = *(const float4*)(rvb + a * NN * DD);
        const float* ep = eb + a * NN * NN;
        #pragma unroll
        for (int x = 0; x < CXT; x++) en[buf][x] = ep[x * NN];
    };

    u64 acc[CXT][2];
    float den[CXT];
    #pragma unroll
    for (int x = 0; x < CXT; x++) {
        den[x] = 0.f;
        acc[x][0] = 0ULL; acc[x][1] = 0ULL;
    }

    ldg_a(0, 0);
    ldg_a(1, 1);
    for (int a = 0; a < NN; a++) {
        const int buf = a & 1;
        float4 r0 = rn[buf];
        float e[CXT];
        #pragma unroll
        for (int x = 0; x < CXT; x++) e[x] = en[buf][x];
        if (a < NN - 2) ldg_a(a + 2, buf);

        u64 rv0 = ((u64*)&r0)[0], rv1 = ((u64*)&r0)[1];

        #pragma unroll
        for (int x = 0; x < CXT; x++) {
            float p = e[x];
            den[x] += p;
            u64 pp = pack2(p, p);
            const u64* lv = (const u64*)&LVs[((x << 6) + a) * DK + qd];
            u64 t0, t1;
            mul2(t0, lv[0], rv0); ffma2(acc[x][0], pp, t0);
            mul2(t1, lv[1], rv1); ffma2(acc[x][1], pp, t1);
        }
    }

    // epilogue: normalize, store bf16 hi/lo (feeds out-projection)
    #pragma unroll
    for (int x = 0; x < CXT; x++) {
        float inv = 1.0f / den[x];
        u64 iv = pack2(inv, inv);
        float o[4];
        u64 v0, v1;
        mul2(v0, acc[x][0], iv);
        mul2(v1, acc[x][1], iv);
        unpack2(v0, o[0], o[1]);
        unpack2(v1, o[2], o[3]);
        uint2 hv, lv2;
        split2(o[0], o[1], hv.x, lv2.x);
        split2(o[2], o[3], hv.y, lv2.y);
        const int m = (b * NN + x0 + x) * NN + y;
        *(uint2*)&Ohi[m * DD + h * DK + qd] = hv;
        *(uint2*)&Olo[m * DD + h * DK + qd] = lv2;
    }
}

// ---------------- launch ----------------
extern "C" void kernel_launch(void* const* d_in, const int* in_sizes, int n_in,
                              void* d_out, int out_size) {
    const float* state = (const float*)d_in[0];
    const unsigned char* mask = (const unsigned char*)d_in[1];
    const float* W_lk = (const float*)d_in[2];
    const float* b_lk = (const float*)d_in[3];
    const float* W_rk = (const float*)d_in[4];
    const float* b_rk = (const float*)d_in[5];
    const float* W_lv = (const float*)d_in[6];
    const float* b_lv = (const float*)d_in[7];
    const float* W_rv = (const float*)d_in[8];
    const float* b_rv = (const float*)d_in[9];
    const float* W_o  = (const float*)d_in[10];
    const float* b_o  = (const float*)d_in[11];
    float* out = (float*)d_out;

    float *lv, *rv, *E;
    __nv_bfloat16 *shi, *slo, *xhi, *xlo, *whi, *wlo, *lkhi, *lklo, *rkhi, *rklo;
    cudaGetSymbolAddress((void**)&lv, g_lv);
    cudaGetSymbolAddress((void**)&rv, g_rv);
    cudaGetSymbolAddress((void**)&E, g_E);
    cudaGetSymbolAddress((void**)&shi, g_shi);
    cudaGetSymbolAddress((void**)&slo, g_slo);
    cudaGetSymbolAddress((void**)&xhi, g_xhi);
    cudaGetSymbolAddress((void**)&xlo, g_xlo);
    cudaGetSymbolAddress((void**)&whi, g_whi);
    cudaGetSymbolAddress((void**)&wlo, g_wlo);
    cudaGetSymbolAddress((void**)&lkhi, g_lkhi);
    cudaGetSymbolAddress((void**)&lklo, g_lklo);
    cudaGetSymbolAddress((void**)&rkhi, g_rkhi);
    cudaGetSymbolAddress((void**)&rklo, g_rklo);

    cudaFuncSetAttribute(gemm_bf16_kernel, cudaFuncAttributeMaxDynamicSharedMemorySize,
                         GEMM_SMEM);
    cudaFuncSetAttribute(scores_kernel, cudaFuncAttributeMaxDynamicSharedMemorySize,
                         SC_SMEM);
    cudaFuncSetAttribute(combine_kernel, cudaFuncAttributeMaxDynamicSharedMemorySize,
                         CMB_SMEM);

    // 0) pre-convert state + all weights to bf16 hi/lo (one kernel)
    WSrc ws;
    ws.w[0] = W_lk; ws.w[1] = W_rk; ws.w[2] = W_lv; ws.w[3] = W_rv; ws.w[4] = W_o;
    conv_all_kernel<<<(NS4 + NW4 + 255) / 256, 256>>>(state, ws, shi, slo, whi, wlo);

    // 1) 4 fused projections: lk/rk as bf16 hi/lo only; lv/rv as fp32 only
    GemmIO pio;
    pio.bias[0] = b_lk; pio.out[0] = nullptr; pio.hi[0] = lkhi; pio.lo[0] = lklo;
    pio.bias[1] = b_rk; pio.out[1] = nullptr; pio.hi[1] = rkhi; pio.lo[1] = rklo;
    pio.bias[2] = b_lv; pio.out[2] = lv;      pio.hi[2] = nullptr; pio.lo[2] = nullptr;
    pio.bias[3] = b_rv; pio.out[3] = rv;      pio.hi[3] = nullptr; pio.lo[3] = nullptr;
    gemm_bf16_kernel<<<dim3(MTOT / 128, 8), 256, GEMM_SMEM>>>(shi, slo, whi, wlo, 0, pio);

    // 2) scores (HMMA) -> E
    scores_kernel<<<dim3(8, 16), 256, SC_SMEM>>>(lkhi, lklo, rkhi, rklo, mask, E);

    // 3) combine -> xhi/xlo (bf16 split, directly consumable by out-proj)
    combine_kernel<<<128, 512, CMB_SMEM>>>(lv, rv, E, xhi, xlo);

    // 4) output projection
    GemmIO fio;
    fio.bias[0] = b_o; fio.out[0] = out; fio.hi[0] = nullptr; fio.lo[0] = nullptr;
    fio.bias[1] = b_o; fio.out[1] = out; fio.hi[1] = nullptr; fio.lo[1] = nullptr;
    fio.bias[2] = b_o; fio.out[2] = out; fio.hi[2] = nullptr; fio.lo[2] = nullptr;
    fio.bias[3] = b_o; fio.out[3] = out; fio.hi[3] = nullptr; fio.lo[3] = nullptr;
    gemm_bf16_kernel<<<dim3(MTOT / 128, 2), 256, GEMM_SMEM>>>(xhi, xlo, whi, wlo, 4, fio);
}

// round 16
// speedup vs baseline: 1.1391x; 1.1391x over previous
#include <cuda_runtime.h>
#include <cuda_bf16.h>
#include <cstdint>

// Problem constants
#define BB 2
#define NN 64
#define DD 256
#define HH 8
#define DK 32
#define MTOT (BB*NN*NN)   // 8192 rows

typedef unsigned long long u64;

// ---------------- scratch (no allocations allowed) ----------------
__device__ float g_lv[MTOT * DD];
__device__ float g_rv[MTOT * DD];
__device__ __nv_bfloat16 g_shi[MTOT * DD];
__device__ __nv_bfloat16 g_slo[MTOT * DD];
__device__ __nv_bfloat16 g_xhi[MTOT * DD];
__device__ __nv_bfloat16 g_xlo[MTOT * DD];
__device__ __nv_bfloat16 g_whi[5 * DD * DD];
__device__ __nv_bfloat16 g_wlo[5 * DD * DD];
__device__ __nv_bfloat16 g_lkhi[MTOT * DD];
__device__ __nv_bfloat16 g_lklo[MTOT * DD];
__device__ __nv_bfloat16 g_rkhi[MTOT * DD];
__device__ __nv_bfloat16 g_rklo[MTOT * DD];
__device__ float g_E[16 * NN * NN * NN];     // [bh][a][x][y]

// ---------------- f32x2 helpers ----------------
__device__ __forceinline__ u64 pack2(float lo, float hi) {
    u64 r; asm("mov.b64 %0, {%1,%2};" : "=l"(r) : "f"(lo), "f"(hi)); return r;
}
__device__ __forceinline__ void unpack2(u64 v, float& lo, float& hi) {
    asm("mov.b64 {%0,%1}, %2;" : "=f"(lo), "=f"(hi) : "l"(v));
}
__device__ __forceinline__ void ffma2(u64& d, u64 a, u64 b) {
    asm("fma.rn.f32x2 %0, %1, %2, %0;" : "+l"(d) : "l"(a), "l"(b));
}
__device__ __forceinline__ void mul2(u64& d, u64 a, u64 b) {
    asm("mul.rn.f32x2 %0, %1, %2;" : "=l"(d) : "l"(a), "l"(b));
}

__device__ __forceinline__ uint32_t smem_u32(const void* p) {
    uint32_t a;
    asm("{ .reg .u64 t; cvta.to.shared.u64 t, %1; cvt.u32.u64 %0, t; }"
        : "=r"(a) : "l"(p));
    return a;
}

// ---------------- HMMA / cp.async helpers -----------------
__device__ __forceinline__ void ldsm_x4(uint32_t& r0, uint32_t& r1,
                                        uint32_t& r2, uint32_t& r3, uint32_t addr) {
    asm volatile("ldmatrix.sync.aligned.m8n8.x4.shared.b16 {%0,%1,%2,%3}, [%4];"
                 : "=r"(r0), "=r"(r1), "=r"(r2), "=r"(r3) : "r"(addr));
}
__device__ __forceinline__ void ldsm_x2(uint32_t& r0, uint32_t& r1, uint32_t addr) {
    asm volatile("ldmatrix.sync.aligned.m8n8.x2.shared.b16 {%0,%1}, [%2];"
                 : "=r"(r0), "=r"(r1) : "r"(addr));
}
__device__ __forceinline__ void mma_bf16(float* c, const uint32_t* a, const uint32_t* b) {
    asm volatile("mma.sync.aligned.m16n8k16.row.col.f32.bf16.bf16.f32 "
                 "{%0,%1,%2,%3}, {%4,%5,%6,%7}, {%8,%9}, {%0,%1,%2,%3};"
                 : "+f"(c[0]), "+f"(c[1]), "+f"(c[2]), "+f"(c[3])
                 : "r"(a[0]), "r"(a[1]), "r"(a[2]), "r"(a[3]), "r"(b[0]), "r"(b[1]));
}
__device__ __forceinline__ void cp_async16(uint32_t dst, const void* src) {
    asm volatile("cp.async.ca.shared.global [%0], [%1], 16;" :: "r"(dst), "l"(src));
}
#define CP_COMMIT() asm volatile("cp.async.commit_group;" ::: "memory")
#define CP_WAIT(N)  asm volatile("cp.async.wait_group %0;" :: "n"(N) : "memory")

// split fp32 -> (hi, lo) bf16 pairs
__device__ __forceinline__ void split4(float4 v, uint2& hi, uint2& lo) {
    __nv_bfloat16 h0 = __float2bfloat16(v.x), h1 = __float2bfloat16(v.y);
    __nv_bfloat16 h2 = __float2bfloat16(v.z), h3 = __float2bfloat16(v.w);
    __nv_bfloat16 l0 = __float2bfloat16(v.x - __bfloat162float(h0));
    __nv_bfloat16 l1 = __float2bfloat16(v.y - __bfloat162float(h1));
    __nv_bfloat16 l2 = __float2bfloat16(v.z - __bfloat162float(h2));
    __nv_bfloat16 l3 = __float2bfloat16(v.w - __bfloat162float(h3));
    __nv_bfloat162 hp0 = __halves2bfloat162(h0, h1);
    __nv_bfloat162 hp1 = __halves2bfloat162(h2, h3);
    __nv_bfloat162 lp0 = __halves2bfloat162(l0, l1);
    __nv_bfloat162 lp1 = __halves2bfloat162(l2, l3);
    hi.x = *(uint32_t*)&hp0; hi.y = *(uint32_t*)&hp1;
    lo.x = *(uint32_t*)&lp0; lo.y = *(uint32_t*)&lp1;
}
__device__ __forceinline__ void split2(float x, float y, uint32_t& hi, uint32_t& lo) {
    __nv_bfloat16 h0 = __float2bfloat16(x), h1 = __float2bfloat16(y);
    __nv_bfloat16 l0 = __float2bfloat16(x - __bfloat162float(h0));
    __nv_bfloat16 l1 = __float2bfloat16(y - __bfloat162float(h1));
    __nv_bfloat162 hp = __halves2bfloat162(h0, h1);
    __nv_bfloat162 lp = __halves2bfloat162(l0, l1);
    hi = *(uint32_t*)&hp; lo = *(uint32_t*)&lp;
}

// ---------------- merged convert kernel (state + all 5 weights) --------
#define NS4 (MTOT * DD / 4)        // 524288 state float4s
#define NW4 (5 * DD * DD / 4)      // 81920 weight float4s
struct WSrc { const float* w[5]; };

__global__ void conv_all_kernel(const float* __restrict__ state, WSrc ws,
                                __nv_bfloat16* __restrict__ shi,
                                __nv_bfloat16* __restrict__ slo,
                                __nv_bfloat16* __restrict__ whi,
                                __nv_bfloat16* __restrict__ wlo)
{
    int i = blockIdx.x * 256 + threadIdx.x;
    if (i < NS4) {
        float4 v = ((const float4*)state)[i];
        uint2 h, l;
        split4(v, h, l);
        ((uint2*)shi)[i] = h;
        ((uint2*)slo)[i] = l;
    } else if (i < NS4 + NW4) {
        int j = i - NS4;
        int which = j >> 14;
        int off = j & 16383;
        float4 v = ((const float4*)ws.w[which])[off];
        uint2 h, l;
        split4(v, h, l);
        ((uint2*)whi)[j] = h;
        ((uint2*)wlo)[j] = l;
    }
}

// ================= bf16-split HMMA GEMM =============
struct GemmIO {
    const float* bias[4];
    float* out[4];
    __nv_bfloat16* hi[4];
    __nv_bfloat16* lo[4];
};

#define GROW 80
#define GMAT (128 * GROW)
#define GSTAGE (4 * GMAT)
#define GEMM_SMEM (2 * GSTAGE)  // 81920

__global__ void __launch_bounds__(256) gemm_bf16_kernel(
    const __nv_bfloat16* __restrict__ Ahi, const __nv_bfloat16* __restrict__ Alo,
    const __nv_bfloat16* __restrict__ Whi, const __nv_bfloat16* __restrict__ Wlo,
    int wbase, GemmIO io)
{
    extern __shared__ unsigned char smg[];
    const uint32_t smb = smem_u32(smg);

    const int tid = threadIdx.x;
    const int wid = tid >> 5;
    const int lane = tid & 31;
    const int m0 = blockIdx.x * 128;
    const int by = blockIdx.y;
    const int sel = by >> 1;
    const int n0 = (by & 1) * 128;
    const int woff = (wbase + sel) * DD * DD;
    const float* __restrict__ bias = io.bias[sel];
    float* __restrict__ C = io.out[sel];
    __nv_bfloat16* __restrict__ Chi = io.hi[sel];
    __nv_bfloat16* __restrict__ Clo = io.lo[sel];

    const int wm = wid & 1;
    const int wn = wid >> 1;

    float acc[4][4][4];
    #pragma unroll
    for (int i = 0; i < 4; i++)
        #pragma unroll
        for (int j = 0; j < 4; j++)
            #pragma unroll
            for (int q = 0; q < 4; q++) acc[i][j][q] = 0.f;

    auto issue = [&](int kt, int st) {
        const int kc = kt * 32;
        const uint32_t sb = smb + st * GSTAGE;
        #pragma unroll
        for (int t = 0; t < 8; t++) {
            int i = tid + (t << 8);
            int mat = t >> 1;
            int r = (i >> 2) & 127;
            int c = i & 3;
            uint32_t dst = sb + mat * GMAT + r * GROW + c * 16;
            const __nv_bfloat16* src;
            if (mat == 0)      src = Ahi + (m0 + r) * DD + kc + c * 8;
            else if (mat == 1) src = Alo + (m0 + r) * DD + kc + c * 8;
            else if (mat == 2) src = Whi + woff + (n0 + r) * DD + kc + c * 8;
            else               src = Wlo + woff + (n0 + r) * DD + kc + c * 8;
            cp_async16(dst, src);
        }
        CP_COMMIT();
    };

    auto compute = [&](int st) {
        const uint32_t sAhi = smb + st * GSTAGE;
        const uint32_t sAlo = sAhi + GMAT;
        const uint32_t sWhi = sAhi + 2 * GMAT;
        const uint32_t sWlo = sAhi + 3 * GMAT;
        #pragma unroll
        for (int ks = 0; ks < 2; ks++) {
            const uint32_t kb = ks * 32;
            uint32_t ah[4][4], al[4][4], bh[4][2], bl[4][2];
            const uint32_t aoff = (wm * 64 + (lane & 15)) * GROW + kb + ((lane >> 4) << 4);
            #pragma unroll
            for (int mi = 0; mi < 4; mi++) {
                ldsm_x4(ah[mi][0], ah[mi][1], ah[mi][2], ah[mi][3],
                        sAhi + aoff + mi * 16 * GROW);
                ldsm_x4(al[mi][0], al[mi][1], al[mi][2], al[mi][3],
                        sAlo + aoff + mi * 16 * GROW);
            }
            const uint32_t boff = (wn * 32 + (lane & 7)) * GROW + kb + (((lane >> 3) & 1) << 4);
            #pragma unroll
            for (int ni = 0; ni < 4; ni++) {
                ldsm_x2(bh[ni][0], bh[ni][1], sWhi + boff + ni * 8 * GROW);
                ldsm_x2(bl[ni][0], bl[ni][1], sWlo + boff + ni * 8 * GROW);
            }
            #pragma unroll
            for (int mi = 0; mi < 4; mi++)
                #pragma unroll
                for (int ni = 0; ni < 4; ni++) mma_bf16(acc[mi][ni], ah[mi], bh[ni]);
            #pragma unroll
            for (int mi = 0; mi < 4; mi++)
                #pragma unroll
                for (int ni = 0; ni < 4; ni++) mma_bf16(acc[mi][ni], ah[mi], bl[ni]);
            #pragma unroll
            for (int mi = 0; mi < 4; mi++)
                #pragma unroll
                for (int ni = 0; ni < 4; ni++) mma_bf16(acc[mi][ni], al[mi], bh[ni]);
        }
    };

    issue(0, 0);
    for (int kt = 0; kt < 8; kt++) {
        if (kt < 7) {
            issue(kt + 1, (kt + 1) & 1);
            CP_WAIT(1);
        } else {
            CP_WAIT(0);
        }
        __syncthreads();
        compute(kt & 1);
        __syncthreads();
    }

    // epilogue: fp32 and/or bf16 hi/lo stores (each optional)
    #pragma unroll
    for (int mi = 0; mi < 4; mi++) {
        const int mlo = m0 + wm * 64 + mi * 16 + (lane >> 2);
        #pragma unroll
        for (int ni = 0; ni < 4; ni++) {
            const int nb = n0 + wn * 32 + ni * 8 + ((lane & 3) << 1);
            const float2 bv = *(const float2*)&bias[nb];
            float2 o0, o1;
            o0.x = acc[mi][ni][0] + bv.x; o0.y = acc[mi][ni][1] + bv.y;
            o1.x = acc[mi][ni][2] + bv.x; o1.y = acc[mi][ni][3] + bv.y;
            if (C) {
                *(float2*)&C[mlo * DD + nb] = o0;
                *(float2*)&C[(mlo + 8) * DD + nb] = o1;
            }
            if (Chi) {
                uint32_t h, l;
                split2(o0.x, o0.y, h, l);
                *(uint32_t*)&Chi[mlo * DD + nb] = h;
                *(uint32_t*)&Clo[mlo * DD + nb] = l;
                split2(o1.x, o1.y, h, l);
                *(uint32_t*)&Chi[(mlo + 8) * DD + nb] = h;
                *(uint32_t*)&Clo[(mlo + 8) * DD + nb] = l;
            }
        }
    }
}

// ================= scores kernel v2 (2 a per stage, 4 warps per a) =====
#define SC_ROW 80
#define SC_MAT (64 * SC_ROW)          // 5120 bytes per matrix
#define SC_A   (4 * SC_MAT)           // 20480 per a
#define SC_STG (2 * SC_A)             // 40960 per stage (2 a)
#define SC_SMEM (2 * SC_STG)          // 81920

__global__ void __launch_bounds__(256) scores_kernel(
    const __nv_bfloat16* __restrict__ LKhi, const __nv_bfloat16* __restrict__ LKlo,
    const __nv_bfloat16* __restrict__ RKhi, const __nv_bfloat16* __restrict__ RKlo,
    const unsigned char* __restrict__ mask, float* __restrict__ E)
{
    extern __shared__ unsigned char sms[];
    const uint32_t smb = smem_u32(sms);
    const int tid = threadIdx.x;
    const int wid = tid >> 5, lane = tid & 31;
    const int bh = blockIdx.y;
    const int b = bh >> 3, h = bh & 7;
    const int a0c = blockIdx.x * 8;
    const int ai = wid >> 2;
    const int wm = wid & 3;

    auto issue = [&](int a0, int st) {
        const uint32_t sb = smb + st * SC_STG;
        #pragma unroll
        for (int t = 0; t < 8; t++) {
            int idx = tid + (t << 8);
            int aidx = idx >> 10;
            int mat = (idx >> 8) & 3;
            int r = (idx >> 2) & 63;
            int c = idx & 3;
            uint32_t dst = sb + aidx * SC_A + mat * SC_MAT + r * SC_ROW + c * 16;
            const int a = a0 + aidx;
            const __nv_bfloat16* src;
            if (mat == 0)      src = LKhi + ((b * NN + r) * NN + a) * DD + h * DK + c * 8;
            else if (mat == 1) src = LKlo + ((b * NN + r) * NN + a) * DD + h * DK + c * 8;
            else if (mat == 2) src = RKhi + ((b * NN + a) * NN + r) * DD + h * DK + c * 8;
            else               src = RKlo + ((b * NN + a) * NN + r) * DD + h * DK + c * 8;
            cp_async16(dst, src);
        }
        CP_COMMIT();
    };

    const float scale = 0.17677669529663687f;   // 1/sqrt(32)

    issue(a0c, 0);
    for (int it = 0; it < 4; it++) {
        const int a = a0c + it * 2 + ai;
        if (it < 3) { issue(a0c + (it + 1) * 2, (it + 1) & 1); CP_WAIT(1); }
        else CP_WAIT(0);
        __syncthreads();

        const uint32_t base = smb + (it & 1) * SC_STG + ai * SC_A;
        const uint32_t sLKh = base, sLKl = base + SC_MAT;
        const uint32_t sRKh = base + 2 * SC_MAT, sRKl = base + 3 * SC_MAT;

        float acc[8][4];
        #pragma unroll
        for (int nf = 0; nf < 8; nf++)
            #pragma unroll
            for (int q = 0; q < 4; q++) acc[nf][q] = 0.f;

        #pragma unroll
        for (int ks = 0; ks < 2; ks++) {
            const uint32_t kb = ks * 32;
            uint32_t ah[4], al[4], bhf[8][2], blf[8][2];
            const uint32_t aoff = (wm * 16 + (lane & 15)) * SC_ROW + kb + ((lane >> 4) << 4);
            ldsm_x4(ah[0], ah[1], ah[2], ah[3], sLKh + aoff);
            ldsm_x4(al[0], al[1], al[2], al[3], sLKl + aoff);
            const uint32_t brow = (lane & 7) + ((lane >> 4) << 3);
            const uint32_t bcol = kb + (((lane >> 3) & 1) << 4);
            #pragma unroll
            for (int nb = 0; nb < 4; nb++) {
                const uint32_t boff = (nb * 16 + brow) * SC_ROW + bcol;
                ldsm_x4(bhf[2 * nb][0], bhf[2 * nb][1], bhf[2 * nb + 1][0],
                        bhf[2 * nb + 1][1], sRKh + boff);
                ldsm_x4(blf[2 * nb][0], blf[2 * nb][1], blf[2 * nb + 1][0],
                        blf[2 * nb + 1][1], sRKl + boff);
            }
            #pragma unroll
            for (int nf = 0; nf < 8; nf++) mma_bf16(acc[nf], ah, bhf[nf]);
            #pragma unroll
            for (int nf = 0; nf < 8; nf++) mma_bf16(acc[nf], ah, blf[nf]);
            #pragma unroll
            for (int nf = 0; nf < 8; nf++) mma_bf16(acc[nf], al, bhf[nf]);
        }

        // exp + mask + store E[bh][a][x][y]
        const int r0 = wm * 16 + (lane >> 2);
        #pragma unroll
        for (int nf = 0; nf < 8; nf++) {
            const int col = nf * 8 + ((lane & 3) << 1);
            const unsigned char* mp0 = mask + ((b * NN + r0) * NN + a) * NN + col;
            const unsigned char* mp1 = mask + ((b * NN + r0 + 8) * NN + a) * NN + col;
            float2 e0, e1;
            e0.x = mp0[0] ? 0.f : __expf(acc[nf][0] * scale);
            e0.y = mp0[1] ? 0.f : __expf(acc[nf][1] * scale);
            e1.x = mp1[0] ? 0.f : __expf(acc[nf][2] * scale);
            e1.y = mp1[1] ? 0.f : __expf(acc[nf][3] * scale);
            float* ep = E + ((bh * NN + a) * NN + r0) * NN + col;
            *(float2*)ep = e0;
            *(float2*)(ep + 8 * NN) = e1;
        }
        __syncthreads();
    }
}

// ================= combine kernel v6 (512 thr, 1 E-LDG + shfl) =========
// out[x,y,d] = (sum_a E[a,x,y]*LV[x,a,d]*RV[a,y,d]) / (sum_a E[a,x,y])
// Thread = (y, d-eighth). Per warp per a: ONE E LDG (32 values = 8x * 4y,
// one per lane) shared via shfl, plus one RV LDG.128. Depth-1 prefetch.
#define CXT 8
#define CMB_SMEM (CXT * NN * DK * 4)    // 65536 bytes (LVs)

__global__ void __launch_bounds__(512) combine_kernel(
    const float* __restrict__ LV, const float* __restrict__ RV,
    const float* __restrict__ E,
    __nv_bfloat16* __restrict__ Ohi, __nv_bfloat16* __restrict__ Olo)
{
    extern __shared__ float LVs[];     // [8x][64a][32d]

    const int tid = threadIdx.x;
    const int blk = blockIdx.x;        // 128 = bh(16)*xt(8)
    const int xt = blk & 7;
    const int bh = blk >> 3;
    const int b = bh >> 3, h = bh & 7;
    const int x0 = xt << 3;

    const int y  = tid >> 3;           // 0..63
    const int q  = tid & 7;            // d-eighth
    const int qd = q << 2;             // 0,4,...,28
    const int lane = tid & 31;
    const int lsrc = lane & ~7;        // ly*8, shfl source base for this thread

    for (int i = tid; i < CXT * NN * DK / 4; i += 512) {
        int xv = i >> 9;
        int a  = (i >> 3) & 63;
        int d4 = (i & 7) << 2;
        *(float4*)&LVs[((xv << 6) + a) * DK + d4] =
            *(const float4*)&LV[((b * NN + x0 + xv) * NN + a) * DD + h * DK + d4];
    }
    __syncthreads();

    const float* rvb = RV + (b * NN * NN + y) * DD + h * DK + qd;
    // E lane-load: lane l holds E[a, x0+(l&7), ybase+(l>>3)], ybase = warp's y base
    const int ex = x0 + (lane & 7);
    const int eyy = (y & ~3) + (lane >> 3);
    const float* ebl = E + (bh * NN + 0) * NN * NN + ex * NN + eyy;  // + a*NN*NN

    float4 rn;
    float evn;
    auto ldg_a = [&](int a) {
        rn = *(const float4*)(rvb + a * NN * DD);
        evn = ebl[a * NN * NN];
    };

    u64 acc[CXT][2];
    float den[CXT];
    #pragma unroll
    for (int x = 0; x < CXT; x++) {
        den[x] = 0.f;
        acc[x][0] = 0ULL; acc[x][1] = 0ULL;
    }

    ldg_a(0);
    for (int a = 0; a < NN; a++) {
        float4 r0 = rn;
        float ev = evn;
        if (a < NN - 1) ldg_a(a + 1);

        u64 rv0 = ((u64*)&r0)[0], rv1 = ((u64*)&r0)[1];

        #pragma unroll
        for (int x = 0; x < CXT; x++) {
            float p = __shfl_sync(0xFFFFFFFFu, ev, lsrc | x);
            den[x] += p;
            u64 pp = pack2(p, p);
            const u64* lv = (const u64*)&LVs[((x << 6) + a) * DK + qd];
            u64 t0, t1;
            mul2(t0, lv[0], rv0); ffma2(acc[x][0], pp, t0);
            mul2(t1, lv[1], rv1); ffma2(acc[x][1], pp, t1);
        }
    }

    // epilogue: normalize, store bf16 hi/lo (feeds out-projection)
    #pragma unroll
    for (int x = 0; x < CXT; x++) {
        float inv = 1.0f / den[x];
        u64 iv = pack2(inv, inv);
        float o[4];
        u64 v0, v1;
        mul2(v0, acc[x][0], iv);
        mul2(v1, acc[x][1], iv);
        unpack2(v0, o[0], o[1]);
        unpack2(v1, o[2], o[3]);
        uint2 hv, lv2;
        split2(o[0], o[1], hv.x, lv2.x);
        split2(o[2], o[3], hv.y, lv2.y);
        const int m = (b * NN + x0 + x) * NN + y;
        *(uint2*)&Ohi[m * DD + h * DK + qd] = hv;
        *(uint2*)&Olo[m * DD + h * DK + qd] = lv2;
    }
}

// ---------------- launch ----------------
extern "C" void kernel_launch(void* const* d_in, const int* in_sizes, int n_in,
                              void* d_out, int out_size) {
    const float* state = (const float*)d_in[0];
    const unsigned char* mask = (const unsigned char*)d_in[1];
    const float* W_lk = (const float*)d_in[2];
    const float* b_lk = (const float*)d_in[3];
    const float* W_rk = (const float*)d_in[4];
    const float* b_rk = (const float*)d_in[5];
    const float* W_lv = (const float*)d_in[6];
    const float* b_lv = (const float*)d_in[7];
    const float* W_rv = (const float*)d_in[8];
    const float* b_rv = (const float*)d_in[9];
    const float* W_o  = (const float*)d_in[10];
    const float* b_o  = (const float*)d_in[11];
    float* out = (float*)d_out;

    float *lv, *rv, *E;
    __nv_bfloat16 *shi, *slo, *xhi, *xlo, *whi, *wlo, *lkhi, *lklo, *rkhi, *rklo;
    cudaGetSymbolAddress((void**)&lv, g_lv);
    cudaGetSymbolAddress((void**)&rv, g_rv);
    cudaGetSymbolAddress((void**)&E, g_E);
    cudaGetSymbolAddress((void**)&shi, g_shi);
    cudaGetSymbolAddress((void**)&slo, g_slo);
    cudaGetSymbolAddress((void**)&xhi, g_xhi);
    cudaGetSymbolAddress((void**)&xlo, g_xlo);
    cudaGetSymbolAddress((void**)&whi, g_whi);
    cudaGetSymbolAddress((void**)&wlo, g_wlo);
    cudaGetSymbolAddress((void**)&lkhi, g_lkhi);
    cudaGetSymbolAddress((void**)&lklo, g_lklo);
    cudaGetSymbolAddress((void**)&rkhi, g_rkhi);
    cudaGetSymbolAddress((void**)&rklo, g_rklo);

    cudaFuncSetAttribute(gemm_bf16_kernel, cudaFuncAttributeMaxDynamicSharedMemorySize,
                         GEMM_SMEM);
    cudaFuncSetAttribute(scores_kernel, cudaFuncAttributeMaxDynamicSharedMemorySize,
                         SC_SMEM);
    cudaFuncSetAttribute(combine_kernel, cudaFuncAttributeMaxDynamicSharedMemorySize,
                         CMB_SMEM);

    // 0) pre-convert state + all weights to bf16 hi/lo (one kernel)
    WSrc ws;
    ws.w[0] = W_lk; ws.w[1] = W_rk; ws.w[2] = W_lv; ws.w[3] = W_rv; ws.w[4] = W_o;
    conv_all_kernel<<<(NS4 + NW4 + 255) / 256, 256>>>(state, ws, shi, slo, whi, wlo);

    // 1) 4 fused projections: lk/rk as bf16 hi/lo only; lv/rv as fp32 only
    GemmIO pio;
    pio.bias[0] = b_lk; pio.out[0] = nullptr; pio.hi[0] = lkhi; pio.lo[0] = lklo;
    pio.bias[1] = b_rk; pio.out[1] = nullptr; pio.hi[1] = rkhi; pio.lo[1] = rklo;
    pio.bias[2] = b_lv; pio.out[2] = lv;      pio.hi[2] = nullptr; pio.lo[2] = nullptr;
    pio.bias[3] = b_rv; pio.out[3] = rv;      pio.hi[3] = nullptr; pio.lo[3] = nullptr;
    gemm_bf16_kernel<<<dim3(MTOT / 128, 8), 256, GEMM_SMEM>>>(shi, slo, whi, wlo, 0, pio);

    // 2) scores (HMMA) -> E
    scores_kernel<<<dim3(8, 16), 256, SC_SMEM>>>(lkhi, lklo, rkhi, rklo, mask, E);

    // 3) combine -> xhi/xlo (bf16 split, directly consumable by out-proj)
    combine_kernel<<<128, 512, CMB_SMEM>>>(lv, rv, E, xhi, xlo);

    // 4) output projection
    GemmIO fio;
    fio.bias[0] = b_o; fio.out[0] = out; fio.hi[0] = nullptr; fio.lo[0] = nullptr;
    fio.bias[1] = b_o; fio.out[1] = out; fio.hi[1] = nullptr; fio.lo[1] = nullptr;
    fio.bias[2] = b_o; fio.out[2] = out; fio.hi[2] = nullptr; fio.lo[2] = nullptr;
    fio.bias[3] = b_o; fio.out[3] = out; fio.hi[3] = nullptr; fio.lo[3] = nullptr;
    gemm_bf16_kernel<<<dim3(MTOT / 128, 2), 256, GEMM_SMEM>>>(xhi, xlo, whi, wlo, 4, fio);
}

// round 17
// speedup vs baseline: 1.2112x; 1.0633x over previous
#include <cuda_runtime.h>
#include <cuda_bf16.h>
#include <cstdint>

// Problem constants
#define BB 2
#define NN 64
#define DD 256
#define HH 8
#define DK 32
#define MTOT (BB*NN*NN)   // 8192 rows

typedef unsigned long long u64;

// ---------------- scratch (no allocations allowed) ----------------
__device__ float g_lv[MTOT * DD];
__device__ float g_rv[MTOT * DD];
__device__ __nv_bfloat16 g_shi[MTOT * DD];
__device__ __nv_bfloat16 g_slo[MTOT * DD];
__device__ __nv_bfloat16 g_xhi[MTOT * DD];
__device__ __nv_bfloat16 g_xlo[MTOT * DD];
__device__ __nv_bfloat16 g_whi[5 * DD * DD];
__device__ __nv_bfloat16 g_wlo[5 * DD * DD];
__device__ __nv_bfloat16 g_lkhi[MTOT * DD];
__device__ __nv_bfloat16 g_lklo[MTOT * DD];
__device__ __nv_bfloat16 g_rkhi[MTOT * DD];
__device__ __nv_bfloat16 g_rklo[MTOT * DD];
__device__ float g_E[16 * NN * NN * NN];     // [bh][a][y][x]  (transposed!)

// ---------------- f32x2 helpers ----------------
__device__ __forceinline__ u64 pack2(float lo, float hi) {
    u64 r; asm("mov.b64 %0, {%1,%2};" : "=l"(r) : "f"(lo), "f"(hi)); return r;
}
__device__ __forceinline__ void unpack2(u64 v, float& lo, float& hi) {
    asm("mov.b64 {%0,%1}, %2;" : "=f"(lo), "=f"(hi) : "l"(v));
}
__device__ __forceinline__ void ffma2(u64& d, u64 a, u64 b) {
    asm("fma.rn.f32x2 %0, %1, %2, %0;" : "+l"(d) : "l"(a), "l"(b));
}
__device__ __forceinline__ void mul2(u64& d, u64 a, u64 b) {
    asm("mul.rn.f32x2 %0, %1, %2;" : "=l"(d) : "l"(a), "l"(b));
}

__device__ __forceinline__ uint32_t smem_u32(const void* p) {
    uint32_t a;
    asm("{ .reg .u64 t; cvta.to.shared.u64 t, %1; cvt.u32.u64 %0, t; }"
        : "=r"(a) : "l"(p));
    return a;
}

// ---------------- HMMA / cp.async helpers -----------------
__device__ __forceinline__ void ldsm_x4(uint32_t& r0, uint32_t& r1,
                                        uint32_t& r2, uint32_t& r3, uint32_t addr) {
    asm volatile("ldmatrix.sync.aligned.m8n8.x4.shared.b16 {%0,%1,%2,%3}, [%4];"
                 : "=r"(r0), "=r"(r1), "=r"(r2), "=r"(r3) : "r"(addr));
}
__device__ __forceinline__ void ldsm_x2(uint32_t& r0, uint32_t& r1, uint32_t addr) {
    asm volatile("ldmatrix.sync.aligned.m8n8.x2.shared.b16 {%0,%1}, [%2];"
                 : "=r"(r0), "=r"(r1) : "r"(addr));
}
__device__ __forceinline__ void mma_bf16(float* c, const uint32_t* a, const uint32_t* b) {
    asm volatile("mma.sync.aligned.m16n8k16.row.col.f32.bf16.bf16.f32 "
                 "{%0,%1,%2,%3}, {%4,%5,%6,%7}, {%8,%9}, {%0,%1,%2,%3};"
                 : "+f"(c[0]), "+f"(c[1]), "+f"(c[2]), "+f"(c[3])
                 : "r"(a[0]), "r"(a[1]), "r"(a[2]), "r"(a[3]), "r"(b[0]), "r"(b[1]));
}
__device__ __forceinline__ void cp_async16(uint32_t dst, const void* src) {
    asm volatile("cp.async.ca.shared.global [%0], [%1], 16;" :: "r"(dst), "l"(src));
}
#define CP_COMMIT() asm volatile("cp.async.commit_group;" ::: "memory")
#define CP_WAIT(N)  asm volatile("cp.async.wait_group %0;" :: "n"(N) : "memory")

// split fp32 -> (hi, lo) bf16 pairs
__device__ __forceinline__ void split4(float4 v, uint2& hi, uint2& lo) {
    __nv_bfloat16 h0 = __float2bfloat16(v.x), h1 = __float2bfloat16(v.y);
    __nv_bfloat16 h2 = __float2bfloat16(v.z), h3 = __float2bfloat16(v.w);
    __nv_bfloat16 l0 = __float2bfloat16(v.x - __bfloat162float(h0));
    __nv_bfloat16 l1 = __float2bfloat16(v.y - __bfloat162float(h1));
    __nv_bfloat16 l2 = __float2bfloat16(v.z - __bfloat162float(h2));
    __nv_bfloat16 l3 = __float2bfloat16(v.w - __bfloat162float(h3));
    __nv_bfloat162 hp0 = __halves2bfloat162(h0, h1);
    __nv_bfloat162 hp1 = __halves2bfloat162(h2, h3);
    __nv_bfloat162 lp0 = __halves2bfloat162(l0, l1);
    __nv_bfloat162 lp1 = __halves2bfloat162(l2, l3);
    hi.x = *(uint32_t*)&hp0; hi.y = *(uint32_t*)&hp1;
    lo.x = *(uint32_t*)&lp0; lo.y = *(uint32_t*)&lp1;
}
__device__ __forceinline__ void split2(float x, float y, uint32_t& hi, uint32_t& lo) {
    __nv_bfloat16 h0 = __float2bfloat16(x), h1 = __float2bfloat16(y);
    __nv_bfloat16 l0 = __float2bfloat16(x - __bfloat162float(h0));
    __nv_bfloat16 l1 = __float2bfloat16(y - __bfloat162float(h1));
    __nv_bfloat162 hp = __halves2bfloat162(h0, h1);
    __nv_bfloat162 lp = __halves2bfloat162(l0, l1);
    hi = *(uint32_t*)&hp; lo = *(uint32_t*)&lp;
}

// ---------------- merged convert kernel (state + all 5 weights) --------
#define NS4 (MTOT * DD / 4)        // 524288 state float4s
#define NW4 (5 * DD * DD / 4)      // 81920 weight float4s
struct WSrc { const float* w[5]; };

__global__ void conv_all_kernel(const float* __restrict__ state, WSrc ws,
                                __nv_bfloat16* __restrict__ shi,
                                __nv_bfloat16* __restrict__ slo,
                                __nv_bfloat16* __restrict__ whi,
                                __nv_bfloat16* __restrict__ wlo)
{
    int i = blockIdx.x * 256 + threadIdx.x;
    if (i < NS4) {
        float4 v = ((const float4*)state)[i];
        uint2 h, l;
        split4(v, h, l);
        ((uint2*)shi)[i] = h;
        ((uint2*)slo)[i] = l;
    } else if (i < NS4 + NW4) {
        int j = i - NS4;
        int which = j >> 14;
        int off = j & 16383;
        float4 v = ((const float4*)ws.w[which])[off];
        uint2 h, l;
        split4(v, h, l);
        ((uint2*)whi)[j] = h;
        ((uint2*)wlo)[j] = l;
    }
}

// ================= bf16-split HMMA GEMM =============
struct GemmIO {
    const float* bias[4];
    float* out[4];
    __nv_bfloat16* hi[4];
    __nv_bfloat16* lo[4];
};

#define GROW 80
#define GMAT (128 * GROW)
#define GSTAGE (4 * GMAT)
#define GEMM_SMEM (2 * GSTAGE)  // 81920

__global__ void __launch_bounds__(256) gemm_bf16_kernel(
    const __nv_bfloat16* __restrict__ Ahi, const __nv_bfloat16* __restrict__ Alo,
    const __nv_bfloat16* __restrict__ Whi, const __nv_bfloat16* __restrict__ Wlo,
    int wbase, GemmIO io)
{
    extern __shared__ unsigned char smg[];
    const uint32_t smb = smem_u32(smg);

    const int tid = threadIdx.x;
    const int wid = tid >> 5;
    const int lane = tid & 31;
    const int m0 = blockIdx.x * 128;
    const int by = blockIdx.y;
    const int sel = by >> 1;
    const int n0 = (by & 1) * 128;
    const int woff = (wbase + sel) * DD * DD;
    const float* __restrict__ bias = io.bias[sel];
    float* __restrict__ C = io.out[sel];
    __nv_bfloat16* __restrict__ Chi = io.hi[sel];
    __nv_bfloat16* __restrict__ Clo = io.lo[sel];

    const int wm = wid & 1;
    const int wn = wid >> 1;

    float acc[4][4][4];
    #pragma unroll
    for (int i = 0; i < 4; i++)
        #pragma unroll
        for (int j = 0; j < 4; j++)
            #pragma unroll
            for (int q = 0; q < 4; q++) acc[i][j][q] = 0.f;

    auto issue = [&](int kt, int st) {
        const int kc = kt * 32;
        const uint32_t sb = smb + st * GSTAGE;
        #pragma unroll
        for (int t = 0; t < 8; t++) {
            int i = tid + (t << 8);
            int mat = t >> 1;
            int r = (i >> 2) & 127;
            int c = i & 3;
            uint32_t dst = sb + mat * GMAT + r * GROW + c * 16;
            const __nv_bfloat16* src;
            if (mat == 0)      src = Ahi + (m0 + r) * DD + kc + c * 8;
            else if (mat == 1) src = Alo + (m0 + r) * DD + kc + c * 8;
            else if (mat == 2) src = Whi + woff + (n0 + r) * DD + kc + c * 8;
            else               src = Wlo + woff + (n0 + r) * DD + kc + c * 8;
            cp_async16(dst, src);
        }
        CP_COMMIT();
    };

    auto compute = [&](int st) {
        const uint32_t sAhi = smb + st * GSTAGE;
        const uint32_t sAlo = sAhi + GMAT;
        const uint32_t sWhi = sAhi + 2 * GMAT;
        const uint32_t sWlo = sAhi + 3 * GMAT;
        #pragma unroll
        for (int ks = 0; ks < 2; ks++) {
            const uint32_t kb = ks * 32;
            uint32_t ah[4][4], al[4][4], bh[4][2], bl[4][2];
            const uint32_t aoff = (wm * 64 + (lane & 15)) * GROW + kb + ((lane >> 4) << 4);
            #pragma unroll
            for (int mi = 0; mi < 4; mi++) {
                ldsm_x4(ah[mi][0], ah[mi][1], ah[mi][2], ah[mi][3],
                        sAhi + aoff + mi * 16 * GROW);
                ldsm_x4(al[mi][0], al[mi][1], al[mi][2], al[mi][3],
                        sAlo + aoff + mi * 16 * GROW);
            }
            const uint32_t boff = (wn * 32 + (lane & 7)) * GROW + kb + (((lane >> 3) & 1) << 4);
            #pragma unroll
            for (int ni = 0; ni < 4; ni++) {
                ldsm_x2(bh[ni][0], bh[ni][1], sWhi + boff + ni * 8 * GROW);
                ldsm_x2(bl[ni][0], bl[ni][1], sWlo + boff + ni * 8 * GROW);
            }
            #pragma unroll
            for (int mi = 0; mi < 4; mi++)
                #pragma unroll
                for (int ni = 0; ni < 4; ni++) mma_bf16(acc[mi][ni], ah[mi], bh[ni]);
            #pragma unroll
            for (int mi = 0; mi < 4; mi++)
                #pragma unroll
                for (int ni = 0; ni < 4; ni++) mma_bf16(acc[mi][ni], ah[mi], bl[ni]);
            #pragma unroll
            for (int mi = 0; mi < 4; mi++)
                #pragma unroll
                for (int ni = 0; ni < 4; ni++) mma_bf16(acc[mi][ni], al[mi], bh[ni]);
        }
    };

    issue(0, 0);
    for (int kt = 0; kt < 8; kt++) {
        if (kt < 7) {
            issue(kt + 1, (kt + 1) & 1);
            CP_WAIT(1);
        } else {
            CP_WAIT(0);
        }
        __syncthreads();
        compute(kt & 1);
        __syncthreads();
    }

    // epilogue: fp32 and/or bf16 hi/lo stores (each optional)
    #pragma unroll
    for (int mi = 0; mi < 4; mi++) {
        const int mlo = m0 + wm * 64 + mi * 16 + (lane >> 2);
        #pragma unroll
        for (int ni = 0; ni < 4; ni++) {
            const int nb = n0 + wn * 32 + ni * 8 + ((lane & 3) << 1);
            const float2 bv = *(const float2*)&bias[nb];
            float2 o0, o1;
            o0.x = acc[mi][ni][0] + bv.x; o0.y = acc[mi][ni][1] + bv.y;
            o1.x = acc[mi][ni][2] + bv.x; o1.y = acc[mi][ni][3] + bv.y;
            if (C) {
                *(float2*)&C[mlo * DD + nb] = o0;
                *(float2*)&C[(mlo + 8) * DD + nb] = o1;
            }
            if (Chi) {
                uint32_t h, l;
                split2(o0.x, o0.y, h, l);
                *(uint32_t*)&Chi[mlo * DD + nb] = h;
                *(uint32_t*)&Clo[mlo * DD + nb] = l;
                split2(o1.x, o1.y, h, l);
                *(uint32_t*)&Chi[(mlo + 8) * DD + nb] = h;
                *(uint32_t*)&Clo[(mlo + 8) * DD + nb] = l;
            }
        }
    }
}

// ================= scores kernel v2b (E stored transposed [a][y][x]) ===
#define SC_ROW 80
#define SC_MAT (64 * SC_ROW)          // 5120 bytes per matrix
#define SC_A   (4 * SC_MAT)           // 20480 per a
#define SC_STG (2 * SC_A)             // 40960 per stage (2 a)
#define SC_SMEM (2 * SC_STG)          // 81920

__global__ void __launch_bounds__(256) scores_kernel(
    const __nv_bfloat16* __restrict__ LKhi, const __nv_bfloat16* __restrict__ LKlo,
    const __nv_bfloat16* __restrict__ RKhi, const __nv_bfloat16* __restrict__ RKlo,
    const unsigned char* __restrict__ mask, float* __restrict__ E)
{
    extern __shared__ unsigned char sms[];
    const uint32_t smb = smem_u32(sms);
    const int tid = threadIdx.x;
    const int wid = tid >> 5, lane = tid & 31;
    const int bh = blockIdx.y;
    const int b = bh >> 3, h = bh & 7;
    const int a0c = blockIdx.x * 8;
    const int ai = wid >> 2;
    const int wm = wid & 3;

    auto issue = [&](int a0, int st) {
        const uint32_t sb = smb + st * SC_STG;
        #pragma unroll
        for (int t = 0; t < 8; t++) {
            int idx = tid + (t << 8);
            int aidx = idx >> 10;
            int mat = (idx >> 8) & 3;
            int r = (idx >> 2) & 63;
            int c = idx & 3;
            uint32_t dst = sb + aidx * SC_A + mat * SC_MAT + r * SC_ROW + c * 16;
            const int a = a0 + aidx;
            const __nv_bfloat16* src;
            if (mat == 0)      src = LKhi + ((b * NN + r) * NN + a) * DD + h * DK + c * 8;
            else if (mat == 1) src = LKlo + ((b * NN + r) * NN + a) * DD + h * DK + c * 8;
            else if (mat == 2) src = RKhi + ((b * NN + a) * NN + r) * DD + h * DK + c * 8;
            else               src = RKlo + ((b * NN + a) * NN + r) * DD + h * DK + c * 8;
            cp_async16(dst, src);
        }
        CP_COMMIT();
    };

    const float scale = 0.17677669529663687f;   // 1/sqrt(32)

    issue(a0c, 0);
    for (int it = 0; it < 4; it++) {
        const int a = a0c + it * 2 + ai;
        if (it < 3) { issue(a0c + (it + 1) * 2, (it + 1) & 1); CP_WAIT(1); }
        else CP_WAIT(0);
        __syncthreads();

        const uint32_t base = smb + (it & 1) * SC_STG + ai * SC_A;
        const uint32_t sLKh = base, sLKl = base + SC_MAT;
        const uint32_t sRKh = base + 2 * SC_MAT, sRKl = base + 3 * SC_MAT;

        float acc[8][4];
        #pragma unroll
        for (int nf = 0; nf < 8; nf++)
            #pragma unroll
            for (int q = 0; q < 4; q++) acc[nf][q] = 0.f;

        #pragma unroll
        for (int ks = 0; ks < 2; ks++) {
            const uint32_t kb = ks * 32;
            uint32_t ah[4], al[4], bhf[8][2], blf[8][2];
            const uint32_t aoff = (wm * 16 + (lane & 15)) * SC_ROW + kb + ((lane >> 4) << 4);
            ldsm_x4(ah[0], ah[1], ah[2], ah[3], sLKh + aoff);
            ldsm_x4(al[0], al[1], al[2], al[3], sLKl + aoff);
            const uint32_t brow = (lane & 7) + ((lane >> 4) << 3);
            const uint32_t bcol = kb + (((lane >> 3) & 1) << 4);
            #pragma unroll
            for (int nb = 0; nb < 4; nb++) {
                const uint32_t boff = (nb * 16 + brow) * SC_ROW + bcol;
                ldsm_x4(bhf[2 * nb][0], bhf[2 * nb][1], bhf[2 * nb + 1][0],
                        bhf[2 * nb + 1][1], sRKh + boff);
                ldsm_x4(blf[2 * nb][0], blf[2 * nb][1], blf[2 * nb + 1][0],
                        blf[2 * nb + 1][1], sRKl + boff);
            }
            #pragma unroll
            for (int nf = 0; nf < 8; nf++) mma_bf16(acc[nf], ah, bhf[nf]);
            #pragma unroll
            for (int nf = 0; nf < 8; nf++) mma_bf16(acc[nf], ah, blf[nf]);
            #pragma unroll
            for (int nf = 0; nf < 8; nf++) mma_bf16(acc[nf], al, bhf[nf]);
        }

        // exp + mask + store E transposed: E[bh][a][y][x]
        const int r0 = wm * 16 + (lane >> 2);          // x
        float* ep = E + ((bh * NN + a) * NN) * NN;     // [y][x]
        #pragma unroll
        for (int nf = 0; nf < 8; nf++) {
            const int col = nf * 8 + ((lane & 3) << 1);  // y
            const unsigned char* mp0 = mask + ((b * NN + r0) * NN + a) * NN + col;
            const unsigned char* mp1 = mask + ((b * NN + r0 + 8) * NN + a) * NN + col;
            float e00 = mp0[0] ? 0.f : __expf(acc[nf][0] * scale);
            float e01 = mp0[1] ? 0.f : __expf(acc[nf][1] * scale);
            float e10 = mp1[0] ? 0.f : __expf(acc[nf][2] * scale);
            float e11 = mp1[1] ? 0.f : __expf(acc[nf][3] * scale);
            ep[col * NN + r0]           = e00;
            ep[(col + 1) * NN + r0]     = e01;
            ep[col * NN + r0 + 8]       = e10;
            ep[(col + 1) * NN + r0 + 8] = e11;
        }
        __syncthreads();
    }
}

// ================= combine kernel v7 (2y per thread, vector E) =========
// out[x,y,d] = (sum_a E[a,y,x]*LV[x,a,d]*RV[a,y,d]) / (sum_a E[a,y,x])
// 512 thr: thread = (y(32), xh(2), q(8)); handles y and y+32, 4 x, 4 d.
// LV read once per y-pair (register reuse), E via LDG.128 (4 contiguous x).
#define CXT 8
#define LVX 2056                          // padded per-x stride (floats)
#define CMB_SMEM (CXT * LVX * 4)          // 65792 bytes

__global__ void __launch_bounds__(512) combine_kernel(
    const float* __restrict__ LV, const float* __restrict__ RV,
    const float* __restrict__ E,
    __nv_bfloat16* __restrict__ Ohi, __nv_bfloat16* __restrict__ Olo)
{
    extern __shared__ float LVs[];     // [8x][64a][32d], x-stride LVX

    const int tid = threadIdx.x;
    const int blk = blockIdx.x;        // 128 = bh(16)*xt(8)
    const int xt = blk & 7;
    const int bh = blk >> 3;
    const int b = bh >> 3, h = bh & 7;
    const int x0 = xt << 3;

    const int q  = tid & 7;            // d-eighth (4 floats)
    const int qd = q << 2;
    const int xh = (tid >> 3) & 1;     // x half
    const int xb = xh << 2;            // 0 or 4
    const int yb = tid >> 4;           // 0..31; y = yb and yb+32

    // LV slab: [x][a][d] with padded x-stride
    for (int i = tid; i < CXT * NN * DK / 4; i += 512) {
        int xv = i >> 9;
        int a  = (i >> 3) & 63;
        int d4 = (i & 7) << 2;
        *(float4*)&LVs[xv * LVX + a * DK + d4] =
            *(const float4*)&LV[((b * NN + x0 + xv) * NN + a) * DD + h * DK + d4];
    }
    __syncthreads();

    const float* rv0b = RV + (b * NN * NN + yb) * DD + h * DK + qd;       // y = yb
    const float* rv1b = rv0b + 32 * DD;                                    // y = yb+32
    const float* e0b  = E + (bh * NN * NN + yb) * NN + x0 + xb;            // [a][y][x]
    const float* e1b  = e0b + 32 * NN;

    float4 rn0, rn1, en0, en1;
    auto ldg_a = [&](int a) {
        rn0 = *(const float4*)(rv0b + a * NN * DD);
        rn1 = *(const float4*)(rv1b + a * NN * DD);
        en0 = *(const float4*)(e0b + a * NN * NN);
        en1 = *(const float4*)(e1b + a * NN * NN);
    };

    u64 acc0[4][2], acc1[4][2];
    float den0[4], den1[4];
    #pragma unroll
    for (int xi = 0; xi < 4; xi++) {
        den0[xi] = 0.f; den1[xi] = 0.f;
        acc0[xi][0] = 0ULL; acc0[xi][1] = 0ULL;
        acc1[xi][0] = 0ULL; acc1[xi][1] = 0ULL;
    }

    ldg_a(0);
    for (int a = 0; a < NN; a++) {
        float4 r0 = rn0, r1 = rn1, e0 = en0, e1 = en1;
        if (a < NN - 1) ldg_a(a + 1);

        u64 rv00 = ((u64*)&r0)[0], rv01 = ((u64*)&r0)[1];
        u64 rv10 = ((u64*)&r1)[0], rv11 = ((u64*)&r1)[1];
        float ev0[4] = {e0.x, e0.y, e0.z, e0.w};
        float ev1[4] = {e1.x, e1.y, e1.z, e1.w};

        #pragma unroll
        for (int xi = 0; xi < 4; xi++) {
            float4 lvv = *(const float4*)&LVs[(xb + xi) * LVX + a * DK + qd];
            u64 l0 = ((u64*)&lvv)[0], l1 = ((u64*)&lvv)[1];
            u64 t0, t1;
            float p0 = ev0[xi];
            den0[xi] += p0;
            u64 pp0 = pack2(p0, p0);
            mul2(t0, l0, rv00); ffma2(acc0[xi][0], pp0, t0);
            mul2(t1, l1, rv01); ffma2(acc0[xi][1], pp0, t1);
            float p1 = ev1[xi];
            den1[xi] += p1;
            u64 pp1 = pack2(p1, p1);
            mul2(t0, l0, rv10); ffma2(acc1[xi][0], pp1, t0);
            mul2(t1, l1, rv11); ffma2(acc1[xi][1], pp1, t1);
        }
    }

    // epilogue: normalize, store bf16 hi/lo (feeds out-projection)
    #pragma unroll
    for (int yy = 0; yy < 2; yy++) {
        const int yv = yb + yy * 32;
        #pragma unroll
        for (int xi = 0; xi < 4; xi++) {
            float dv = yy ? den1[xi] : den0[xi];
            const u64* av = yy ? acc1[xi] : acc0[xi];
            float inv = 1.0f / dv;
            u64 iv = pack2(inv, inv);
            float o[4];
            u64 v0, v1;
            mul2(v0, av[0], iv);
            mul2(v1, av[1], iv);
            unpack2(v0, o[0], o[1]);
            unpack2(v1, o[2], o[3]);
            uint2 hv, lv2;
            split2(o[0], o[1], hv.x, lv2.x);
            split2(o[2], o[3], hv.y, lv2.y);
            const int m = (b * NN + x0 + xb + xi) * NN + yv;
            *(uint2*)&Ohi[m * DD + h * DK + qd] = hv;
            *(uint2*)&Olo[m * DD + h * DK + qd] = lv2;
        }
    }
}

// ---------------- launch ----------------
extern "C" void kernel_launch(void* const* d_in, const int* in_sizes, int n_in,
                              void* d_out, int out_size) {
    const float* state = (const float*)d_in[0];
    const unsigned char* mask = (const unsigned char*)d_in[1];
    const float* W_lk = (const float*)d_in[2];
    const float* b_lk = (const float*)d_in[3];
    const float* W_rk = (const float*)d_in[4];
    const float* b_rk = (const float*)d_in[5];
    const float* W_lv = (const float*)d_in[6];
    const float* b_lv = (const float*)d_in[7];
    const float* W_rv = (const float*)d_in[8];
    const float* b_rv = (const float*)d_in[9];
    const float* W_o  = (const float*)d_in[10];
    const float* b_o  = (const float*)d_in[11];
    float* out = (float*)d_out;

    float *lv, *rv, *E;
    __nv_bfloat16 *shi, *slo, *xhi, *xlo, *whi, *wlo, *lkhi, *lklo, *rkhi, *rklo;
    cudaGetSymbolAddress((void**)&lv, g_lv);
    cudaGetSymbolAddress((void**)&rv, g_rv);
    cudaGetSymbolAddress((void**)&E, g_E);
    cudaGetSymbolAddress((void**)&shi, g_shi);
    cudaGetSymbolAddress((void**)&slo, g_slo);
    cudaGetSymbolAddress((void**)&xhi, g_xhi);
    cudaGetSymbolAddress((void**)&xlo, g_xlo);
    cudaGetSymbolAddress((void**)&whi, g_whi);
    cudaGetSymbolAddress((void**)&wlo, g_wlo);
    cudaGetSymbolAddress((void**)&lkhi, g_lkhi);
    cudaGetSymbolAddress((void**)&lklo, g_lklo);
    cudaGetSymbolAddress((void**)&rkhi, g_rkhi);
    cudaGetSymbolAddress((void**)&rklo, g_rklo);

    cudaFuncSetAttribute(gemm_bf16_kernel, cudaFuncAttributeMaxDynamicSharedMemorySize,
                         GEMM_SMEM);
    cudaFuncSetAttribute(scores_kernel, cudaFuncAttributeMaxDynamicSharedMemorySize,
                         SC_SMEM);
    cudaFuncSetAttribute(combine_kernel, cudaFuncAttributeMaxDynamicSharedMemorySize,
                         CMB_SMEM);

    // 0) pre-convert state + all weights to bf16 hi/lo (one kernel)
    WSrc ws;
    ws.w[0] = W_lk; ws.w[1] = W_rk; ws.w[2] = W_lv; ws.w[3] = W_rv; ws.w[4] = W_o;
    conv_all_kernel<<<(NS4 + NW4 + 255) / 256, 256>>>(state, ws, shi, slo, whi, wlo);

    // 1) 4 fused projections: lk/rk as bf16 hi/lo only; lv/rv as fp32 only
    GemmIO pio;
    pio.bias[0] = b_lk; pio.out[0] = nullptr; pio.hi[0] = lkhi; pio.lo[0] = lklo;
    pio.bias[1] = b_rk; pio.out[1] = nullptr; pio.hi[1] = rkhi; pio.lo[1] = rklo;
    pio.bias[2] = b_lv; pio.out[2] = lv;      pio.hi[2] = nullptr; pio.lo[2] = nullptr;
    pio.bias[3] = b_rv; pio.out[3] = rv;      pio.hi[3] = nullptr; pio.lo[3] = nullptr;
    gemm_bf16_kernel<<<dim3(MTOT / 128, 8), 256, GEMM_SMEM>>>(shi, slo, whi, wlo, 0, pio);

    // 2) scores (HMMA) -> E (transposed [bh][a][y][x])
    scores_kernel<<<dim3(8, 16), 256, SC_SMEM>>>(lkhi, lklo, rkhi, rklo, mask, E);

    // 3) combine -> xhi/xlo (bf16 split, directly consumable by out-proj)
    combine_kernel<<<128, 512, CMB_SMEM>>>(lv, rv, E, xhi, xlo);

    // 4) output projection
    GemmIO fio;
    fio.bias[0] = b_o; fio.out[0] = out; fio.hi[0] = nullptr; fio.lo[0] = nullptr;
    fio.bias[1] = b_o; fio.out[1] = out; fio.hi[1] = nullptr; fio.lo[1] = nullptr;
    fio.bias[2] = b_o; fio.out[2] = out; fio.hi[2] = nullptr; fio.lo[2] = nullptr;
    fio.bias[3] = b_o; fio.out[3] = out; fio.hi[3] = nullptr; fio.lo[3] = nullptr;
    gemm_bf16_kernel<<<dim3(MTOT / 128, 2), 256, GEMM_SMEM>>>(xhi, xlo, whi, wlo, 4, fio);
}